// round 4
// baseline (speedup 1.0000x reference)
#include <cuda_runtime.h>
#include <cstdint>

#define NN   100000
#define FEAT 64
#define INC  128

// Scratch (device globals — no allocation allowed anywhere)
__device__ float g_deg[NN];
__device__ float g_dinv[NN];
__device__ float g_s[NN];                               // row sums of A_hat (b1 term)
__device__ __align__(16) float g_H[(size_t)NN * FEAT];  // X @ (W1 W2)
__device__ __align__(16) float g_T[(size_t)NN * FEAT];  // A_hat @ H
__device__ float g_Wc[INC * FEAT];                      // W1 @ W2
__device__ float g_bW[FEAT];                            // b1 @ W2

// ---------------------------------------------------------------------------
__global__ void k_init_deg(int n) {
    int i = blockIdx.x * blockDim.x + threadIdx.x;
    if (i < n) g_deg[i] = 1.0f;  // self-loop
}

__global__ void k_count_deg(const int* __restrict__ dst, int E) {
    int e = blockIdx.x * blockDim.x + threadIdx.x;
    if (e < E) {
        unsigned d = (unsigned)dst[e];
        if (d < NN) atomicAdd(&g_deg[d], 1.0f);
    }
}

__global__ void k_dinv(int n) {
    int i = blockIdx.x * blockDim.x + threadIdx.x;
    if (i < n) g_dinv[i] = rsqrtf(g_deg[i]);  // deg >= 1 always (self loop)
}

// Wc = W1 @ W2  (128x128 @ 128x64), bW = b1 @ W2
__global__ void k_small(const float* __restrict__ W1,
                        const float* __restrict__ b1,
                        const float* __restrict__ W2) {
    int t = blockIdx.x * blockDim.x + threadIdx.x;
    if (t < INC * FEAT) {
        int k = t >> 6, c = t & 63;
        float acc = 0.f;
        #pragma unroll 8
        for (int j = 0; j < INC; j++)
            acc += W1[k * INC + j] * W2[j * FEAT + c];
        g_Wc[t] = acc;
    }
    if (t < FEAT) {
        float acc = 0.f;
        #pragma unroll 8
        for (int j = 0; j < INC; j++)
            acc += b1[j] * W2[j * FEAT + t];
        g_bW[t] = acc;
    }
}

// H = X @ Wc   (N x 128) @ (128 x 64).  One warp per row, Wc in shared.
__global__ void __launch_bounds__(256) k_gemm(const float* __restrict__ x, int n) {
    __shared__ float sW[INC * FEAT];   // 32 KB
    __shared__ float sx[8][INC];
    for (int i = threadIdx.x; i < INC * FEAT; i += blockDim.x) sW[i] = g_Wc[i];
    __syncthreads();

    int w = threadIdx.x >> 5, lane = threadIdx.x & 31;
    for (int row = blockIdx.x * 8 + w; row < n; row += gridDim.x * 8) {
        float4 xv = reinterpret_cast<const float4*>(x + (size_t)row * INC)[lane];
        sx[w][lane * 4 + 0] = xv.x;
        sx[w][lane * 4 + 1] = xv.y;
        sx[w][lane * 4 + 2] = xv.z;
        sx[w][lane * 4 + 3] = xv.w;
        __syncwarp();

        float a0 = 0.f, a1 = 0.f;
        #pragma unroll
        for (int k = 0; k < INC; k++) {
            float xk = sx[w][k];
            a0 += xk * sW[k * FEAT + lane];
            a1 += xk * sW[k * FEAT + lane + 32];
        }
        float* Hp = g_H + (size_t)row * FEAT;
        Hp[lane]      = a0;
        Hp[lane + 32] = a1;
        __syncwarp();
    }
}

// T[i] = H[i] * dinv[i]^2 (self-loop contribution);  s[i] = dinv[i]^2
__global__ void k_selfT(int n) {
    int idx = blockIdx.x * blockDim.x + threadIdx.x;
    if (idx < n * FEAT) {
        int i = idx >> 6;
        float d = g_dinv[i];
        float d2 = d * d;
        g_T[idx] = g_H[idx] * d2;
        if ((idx & 63) == 0) g_s[i] = d2;
    }
}

// Vectorized f32 reduction (no return), PTX ISA 8.1+ / sm_90+
__device__ __forceinline__ void red4(float* p, float4 v) {
    asm volatile("red.global.add.v4.f32 [%0], {%1,%2,%3,%4};"
                 :: "l"(p), "f"(v.x), "f"(v.y), "f"(v.z), "f"(v.w)
                 : "memory");
}

// Propagation 1: T[dst] += H[src] * norm ; s[dst] += norm
// 16 lanes per edge, one float4 per lane.
__global__ void __launch_bounds__(256) k_prop1(const int* __restrict__ src,
                                               const int* __restrict__ dst,
                                               int E) {
    long long tid = (long long)blockIdx.x * blockDim.x + threadIdx.x;
    int e = (int)(tid >> 4);
    if (e >= E) return;
    int li = threadIdx.x & 15;
    unsigned s = (unsigned)src[e], d = (unsigned)dst[e];
    if (s >= NN || d >= NN) return;
    float norm = g_dinv[s] * g_dinv[d];
    float4 v = reinterpret_cast<const float4*>(g_H + (size_t)s * FEAT)[li];
    v.x *= norm; v.y *= norm; v.z *= norm; v.w *= norm;
    red4(g_T + (size_t)d * FEAT + li * 4, v);
    if (li == 0) atomicAdd(&g_s[d], norm);
}

// out[i] = T[i]*dinv[i]^2 + s[i]*bW + b2   (self loop of 2nd prop + bias terms)
__global__ void k_initout(const float* __restrict__ b2, float* __restrict__ out, int n) {
    int idx = blockIdx.x * blockDim.x + threadIdx.x;
    if (idx < n * FEAT) {
        int i = idx >> 6, c = idx & 63;
        float d = g_dinv[i];
        out[idx] = g_T[idx] * d * d + g_s[i] * g_bW[c] + b2[c];
    }
}

// Propagation 2: out[dst] += T[src] * norm
__global__ void __launch_bounds__(256) k_prop2(const int* __restrict__ src,
                                               const int* __restrict__ dst,
                                               float* __restrict__ out,
                                               int E) {
    long long tid = (long long)blockIdx.x * blockDim.x + threadIdx.x;
    int e = (int)(tid >> 4);
    if (e >= E) return;
    int li = threadIdx.x & 15;
    unsigned s = (unsigned)src[e], d = (unsigned)dst[e];
    if (s >= NN || d >= NN) return;
    float norm = g_dinv[s] * g_dinv[d];
    float4 v = reinterpret_cast<const float4*>(g_T + (size_t)s * FEAT)[li];
    v.x *= norm; v.y *= norm; v.z *= norm; v.w *= norm;
    red4(out + (size_t)d * FEAT + li * 4, v);
}

// ---------------------------------------------------------------------------
extern "C" void kernel_launch(void* const* d_in, const int* in_sizes, int n_in,
                              void* d_out, int out_size) {
    const float* x   = (const float*)d_in[0];
    const int*   ei  = (const int*)d_in[1];    // int64 downcast to int32 by harness
    const float* W1  = (const float*)d_in[2];
    const float* b1  = (const float*)d_in[3];
    const float* W2  = (const float*)d_in[4];
    const float* b2  = (const float*)d_in[5];
    float* out = (float*)d_out;

    int n = in_sizes[0] / INC;          // 100000
    int E = in_sizes[1] / 2;            // 3200000
    const int* srcp = ei;
    const int* dstp = ei + E;

    k_init_deg<<<(n + 255) / 256, 256>>>(n);
    k_count_deg<<<(E + 255) / 256, 256>>>(dstp, E);
    k_dinv<<<(n + 255) / 256, 256>>>(n);
    k_small<<<(INC * FEAT + 255) / 256, 256>>>(W1, b1, W2);
    k_gemm<<<(n + 7) / 8, 256>>>(x, n);
    k_selfT<<<(n * FEAT + 255) / 256, 256>>>(n);
    long long pt = (long long)E * 16;
    k_prop1<<<(unsigned)((pt + 255) / 256), 256>>>(srcp, dstp, E);
    k_initout<<<(n * FEAT + 255) / 256, 256>>>(b2, out, n);
    k_prop2<<<(unsigned)((pt + 255) / 256), 256>>>(srcp, dstp, out, E);
}

// round 8
// speedup vs baseline: 1.7507x; 1.7507x over previous
#include <cuda_runtime.h>
#include <cstdint>

#define NN    100000
#define FEAT  64
#define INC   128
#define EMAX  3400000
#define SB    256
#define NBLK1 ((NN + SB - 1) / SB)        // 391

// Scratch (device globals — no allocation allowed anywhere)
__device__ int   g_cnt[NN];
__device__ int   g_rowstart[NN];
__device__ int   g_cursor[NN];
__device__ int   g_bsum[NBLK1];
__device__ int   g_boff[NBLK1];
__device__ int   g_csr_src[EMAX];
__device__ float g_dinv[NN];
__device__ __align__(16) float g_H[(size_t)NN * FEAT];  // X @ (W1 W2)
__device__ __align__(16) float g_T[(size_t)NN * FEAT];  // A_hat @ H
__device__ __align__(16) float g_Wc[INC * FEAT];        // W1 @ W2
__device__ __align__(16) float g_bW[FEAT];              // b1 @ W2

// ---------------------------------------------------------------------------
__global__ void k_zero(int n) {
    int i = blockIdx.x * blockDim.x + threadIdx.x;
    if (i < n) g_cnt[i] = 0;
}

__global__ void k_histo(const int* __restrict__ dst, int E) {
    int e = blockIdx.x * blockDim.x + threadIdx.x;
    if (e < E) {
        unsigned d = (unsigned)dst[e];
        if (d < NN) atomicAdd(&g_cnt[d], 1);
    }
}

// Level-1 scan: 256-thread blocks, warp-shuffle based. Inclusive prefix to
// g_rowstart (temp), block total to g_bsum.
__global__ void __launch_bounds__(SB) k_scan1(int n) {
    __shared__ int wsum[8];
    int i = blockIdx.x * SB + threadIdx.x;
    int lane = threadIdx.x & 31, w = threadIdx.x >> 5;
    int v = (i < n) ? g_cnt[i] : 0;
    int xv = v;
    #pragma unroll
    for (int off = 1; off < 32; off <<= 1) {
        int t = __shfl_up_sync(0xffffffffu, xv, off);
        if (lane >= off) xv += t;
    }
    if (lane == 31) wsum[w] = xv;
    __syncthreads();
    if (w == 0) {
        int s = (lane < 8) ? wsum[lane] : 0;
        #pragma unroll
        for (int off = 1; off < 8; off <<= 1) {
            int t = __shfl_up_sync(0xffffffffu, s, off);
            if (lane >= off) s += t;
        }
        if (lane < 8) wsum[lane] = s;
    }
    __syncthreads();
    int incl = xv + ((w > 0) ? wsum[w - 1] : 0);
    if (i < n) g_rowstart[i] = incl;
    if (threadIdx.x == SB - 1) g_bsum[blockIdx.x] = incl;
}

// Level-2: one 512-thread block scans the NBLK1 block totals (exclusive).
__global__ void __launch_bounds__(512) k_scan2() {
    __shared__ int sh[512];
    int t = threadIdx.x;
    int v = (t < NBLK1) ? g_bsum[t] : 0;
    sh[t] = v;
    __syncthreads();
    for (int off = 1; off < 512; off <<= 1) {
        int tv = (t >= off) ? sh[t - off] : 0;
        __syncthreads();
        sh[t] += tv;
        __syncthreads();
    }
    if (t < NBLK1) g_boff[t] = sh[t] - v;   // exclusive prefix
}

// rowstart = exclusive global prefix; cursor = rowstart; dinv = rsqrt(cnt+1)
__global__ void k_scan3(int n) {
    int i = blockIdx.x * blockDim.x + threadIdx.x;
    if (i < n) {
        int c = g_cnt[i];
        int start = g_rowstart[i] - c + g_boff[i / SB];
        g_rowstart[i] = start;
        g_cursor[i]   = start;
        g_dinv[i]     = rsqrtf((float)(c + 1));   // + self-loop
    }
}

__global__ void k_scatter(const int* __restrict__ src, const int* __restrict__ dst,
                          int E) {
    int e = blockIdx.x * blockDim.x + threadIdx.x;
    if (e < E) {
        unsigned d = (unsigned)dst[e];
        unsigned s = (unsigned)src[e];
        if (d < NN && s < NN) {
            int pos = atomicAdd(&g_cursor[d], 1);
            if ((unsigned)pos < EMAX) g_csr_src[pos] = (int)s;  // defensive
        }
    }
}

// Wc row k = W1[k,:] @ W2 ; block 128 computes bW = b1 @ W2. 129 blocks x 64 thr.
__global__ void __launch_bounds__(64) k_small(const float* __restrict__ W1,
                                              const float* __restrict__ b1,
                                              const float* __restrict__ W2) {
    __shared__ float sA[INC];
    int k = blockIdx.x;
    const float* arow = (k < INC) ? (W1 + k * INC) : b1;
    for (int i = threadIdx.x; i < INC; i += 64) sA[i] = arow[i];
    __syncthreads();
    int c = threadIdx.x;
    float acc = 0.f;
    #pragma unroll 16
    for (int j = 0; j < INC; j++) acc += sA[j] * W2[j * FEAT + c];
    if (k < INC) g_Wc[k * FEAT + c] = acc;
    else         g_bW[c] = acc;
}

// H = X @ Wc   (N x 128) @ (128 x 64).  One warp per row, Wc in shared.
__global__ void __launch_bounds__(256) k_gemm(const float* __restrict__ x, int n) {
    __shared__ float sW[INC * FEAT];   // 32 KB
    __shared__ float sx[8][INC];
    for (int i = threadIdx.x; i < INC * FEAT; i += blockDim.x) sW[i] = g_Wc[i];
    __syncthreads();

    int w = threadIdx.x >> 5, lane = threadIdx.x & 31;
    for (int row = blockIdx.x * 8 + w; row < n; row += gridDim.x * 8) {
        float4 xv = reinterpret_cast<const float4*>(x + (size_t)row * INC)[lane];
        sx[w][lane * 4 + 0] = xv.x;
        sx[w][lane * 4 + 1] = xv.y;
        sx[w][lane * 4 + 2] = xv.z;
        sx[w][lane * 4 + 3] = xv.w;
        __syncwarp();

        float a0 = 0.f, a1 = 0.f;
        #pragma unroll
        for (int k = 0; k < INC; k++) {
            float xk = sx[w][k];
            a0 += xk * sW[k * FEAT + lane];
            a1 += xk * sW[k * FEAT + lane + 32];
        }
        float* Hp = g_H + (size_t)row * FEAT;
        Hp[lane]      = a0;
        Hp[lane + 32] = a1;
        __syncwarp();
    }
}

// Defensive row-window clamp: guarantees termination + in-bounds even if the
// scan pipeline ever produced garbage.
__device__ __forceinline__ void clamp_row(int& beg, int& cnt) {
    if (beg < 0 || beg >= EMAX) { beg = 0; cnt = 0; }
    if (cnt < 0) cnt = 0;
    if (cnt > EMAX - beg) cnt = EMAX - beg;
}

// CSR propagation 1: T[d] = dinv[d]^2 * H[d] + sum_e dinv[s]*dinv[d]*H[s]
// 16 lanes (half-warp) per destination row; each lane owns one float4.
__global__ void __launch_bounds__(256) k_prop1(int n) {
    int row = (blockIdx.x * 256 + threadIdx.x) >> 4;
    if (row >= n) return;
    int li = threadIdx.x & 15;
    const float4* H4 = reinterpret_cast<const float4*>(g_H);
    float dv = g_dinv[row];
    int beg = g_rowstart[row], cnt = g_cnt[row];
    clamp_row(beg, cnt);

    float4 acc = H4[(size_t)row * 16 + li];
    float d2 = dv * dv;
    acc.x *= d2; acc.y *= d2; acc.z *= d2; acc.w *= d2;

    int k = 0;
    for (; k + 4 <= cnt; k += 4) {
        int s0 = g_csr_src[beg + k + 0] & (unsigned)0x7fffffff;
        int s1 = g_csr_src[beg + k + 1];
        int s2 = g_csr_src[beg + k + 2];
        int s3 = g_csr_src[beg + k + 3];
        s0 = (unsigned)s0 < NN ? s0 : 0;  s1 = (unsigned)s1 < NN ? s1 : 0;
        s2 = (unsigned)s2 < NN ? s2 : 0;  s3 = (unsigned)s3 < NN ? s3 : 0;
        float n0 = dv * g_dinv[s0], n1 = dv * g_dinv[s1];
        float n2 = dv * g_dinv[s2], n3 = dv * g_dinv[s3];
        float4 v0 = H4[(size_t)s0 * 16 + li];
        float4 v1 = H4[(size_t)s1 * 16 + li];
        float4 v2 = H4[(size_t)s2 * 16 + li];
        float4 v3 = H4[(size_t)s3 * 16 + li];
        acc.x += v0.x * n0 + v1.x * n1 + v2.x * n2 + v3.x * n3;
        acc.y += v0.y * n0 + v1.y * n1 + v2.y * n2 + v3.y * n3;
        acc.z += v0.z * n0 + v1.z * n1 + v2.z * n2 + v3.z * n3;
        acc.w += v0.w * n0 + v1.w * n1 + v2.w * n2 + v3.w * n3;
    }
    for (; k < cnt; k++) {
        int s = g_csr_src[beg + k];
        s = (unsigned)s < NN ? s : 0;
        float nm = dv * g_dinv[s];
        float4 v = H4[(size_t)s * 16 + li];
        acc.x += v.x * nm; acc.y += v.y * nm; acc.z += v.z * nm; acc.w += v.w * nm;
    }
    reinterpret_cast<float4*>(g_T)[(size_t)row * 16 + li] = acc;
}

// CSR propagation 2 + epilogue:
// out[d] = dinv^2*T[d] + sum nm*T[s] + (dinv^2 + sum nm)*bW + b2
__global__ void __launch_bounds__(256) k_prop2(const float* __restrict__ b2,
                                               float* __restrict__ out, int n) {
    int row = (blockIdx.x * 256 + threadIdx.x) >> 4;
    if (row >= n) return;
    int li = threadIdx.x & 15;
    const float4* T4 = reinterpret_cast<const float4*>(g_T);
    float dv = g_dinv[row];
    int beg = g_rowstart[row], cnt = g_cnt[row];
    clamp_row(beg, cnt);

    float d2 = dv * dv;
    float sn = d2;                      // row sum of A_hat
    float4 acc = T4[(size_t)row * 16 + li];
    acc.x *= d2; acc.y *= d2; acc.z *= d2; acc.w *= d2;

    int k = 0;
    for (; k + 4 <= cnt; k += 4) {
        int s0 = g_csr_src[beg + k + 0];
        int s1 = g_csr_src[beg + k + 1];
        int s2 = g_csr_src[beg + k + 2];
        int s3 = g_csr_src[beg + k + 3];
        s0 = (unsigned)s0 < NN ? s0 : 0;  s1 = (unsigned)s1 < NN ? s1 : 0;
        s2 = (unsigned)s2 < NN ? s2 : 0;  s3 = (unsigned)s3 < NN ? s3 : 0;
        float n0 = dv * g_dinv[s0], n1 = dv * g_dinv[s1];
        float n2 = dv * g_dinv[s2], n3 = dv * g_dinv[s3];
        float4 v0 = T4[(size_t)s0 * 16 + li];
        float4 v1 = T4[(size_t)s1 * 16 + li];
        float4 v2 = T4[(size_t)s2 * 16 + li];
        float4 v3 = T4[(size_t)s3 * 16 + li];
        sn += n0 + n1 + n2 + n3;
        acc.x += v0.x * n0 + v1.x * n1 + v2.x * n2 + v3.x * n3;
        acc.y += v0.y * n0 + v1.y * n1 + v2.y * n2 + v3.y * n3;
        acc.z += v0.z * n0 + v1.z * n1 + v2.z * n2 + v3.z * n3;
        acc.w += v0.w * n0 + v1.w * n1 + v2.w * n2 + v3.w * n3;
    }
    for (; k < cnt; k++) {
        int s = g_csr_src[beg + k];
        s = (unsigned)s < NN ? s : 0;
        float nm = dv * g_dinv[s];
        float4 v = T4[(size_t)s * 16 + li];
        sn += nm;
        acc.x += v.x * nm; acc.y += v.y * nm; acc.z += v.z * nm; acc.w += v.w * nm;
    }

    float4 bw  = reinterpret_cast<const float4*>(g_bW)[li];
    float4 b2v = reinterpret_cast<const float4*>(b2)[li];
    acc.x += sn * bw.x + b2v.x;
    acc.y += sn * bw.y + b2v.y;
    acc.z += sn * bw.z + b2v.z;
    acc.w += sn * bw.w + b2v.w;
    reinterpret_cast<float4*>(out)[(size_t)row * 16 + li] = acc;
}

// ---------------------------------------------------------------------------
extern "C" void kernel_launch(void* const* d_in, const int* in_sizes, int n_in,
                              void* d_out, int out_size) {
    const float* x   = (const float*)d_in[0];
    const int*   ei  = (const int*)d_in[1];    // int64 downcast to int32 by harness
    const float* W1  = (const float*)d_in[2];
    const float* b1  = (const float*)d_in[3];
    const float* W2  = (const float*)d_in[4];
    const float* b2  = (const float*)d_in[5];
    float* out = (float*)d_out;

    int n = in_sizes[0] / INC;          // 100000
    int E = in_sizes[1] / 2;            // 3200000
    const int* srcp = ei;
    const int* dstp = ei + E;

    k_zero<<<(n + 255) / 256, 256>>>(n);
    k_histo<<<(E + 255) / 256, 256>>>(dstp, E);
    k_scan1<<<NBLK1, SB>>>(n);
    k_scan2<<<1, 512>>>();
    k_scan3<<<(n + 255) / 256, 256>>>(n);
    k_scatter<<<(E + 255) / 256, 256>>>(srcp, dstp, E);
    k_small<<<INC + 1, 64>>>(W1, b1, W2);
    k_gemm<<<(n + 7) / 8, 256>>>(x, n);
    int pgrid = (n * 16 + 255) / 256;
    k_prop1<<<pgrid, 256>>>(n);
    k_prop2<<<pgrid, 256>>>(b2, out, n);
}

// round 9
// speedup vs baseline: 1.9759x; 1.1287x over previous
#include <cuda_runtime.h>
#include <cuda_fp16.h>
#include <cstdint>

#define NN    100000
#define FEAT  64
#define INC   128
#define EMAX  3400000
#define SB    256
#define NBLK1 ((NN + SB - 1) / SB)        // 391

// Scratch (device globals — no allocation allowed anywhere)
__device__ int   g_cnt[NN];
__device__ int   g_rowstart[NN];
__device__ int   g_cursor[NN];
__device__ int   g_bsum[NBLK1];
__device__ int   g_boff[NBLK1];
__device__ int   g_csr_src[EMAX];
__device__ float g_dinv[NN];
__device__ __align__(16) __half g_Hh[(size_t)NN * FEAT];  // X @ (W1 W2), fp16
__device__ __align__(16) __half g_Th[(size_t)NN * FEAT];  // A_hat @ H, fp16
__device__ __align__(16) float  g_Wc[INC * FEAT];         // W1 @ W2
__device__ __align__(16) float  g_bW[FEAT];               // b1 @ W2

// ---------------------------------------------------------------------------
__global__ void k_zero(int n) {
    int i = blockIdx.x * blockDim.x + threadIdx.x;
    if (i < n) g_cnt[i] = 0;
}

__global__ void k_histo(const int* __restrict__ dst, int E) {
    int e = blockIdx.x * blockDim.x + threadIdx.x;
    if (e < E) {
        unsigned d = (unsigned)dst[e];
        if (d < NN) atomicAdd(&g_cnt[d], 1);
    }
}

// Level-1 scan: 256-thread blocks, warp-shuffle based.
__global__ void __launch_bounds__(SB) k_scan1(int n) {
    __shared__ int wsum[8];
    int i = blockIdx.x * SB + threadIdx.x;
    int lane = threadIdx.x & 31, w = threadIdx.x >> 5;
    int v = (i < n) ? g_cnt[i] : 0;
    int xv = v;
    #pragma unroll
    for (int off = 1; off < 32; off <<= 1) {
        int t = __shfl_up_sync(0xffffffffu, xv, off);
        if (lane >= off) xv += t;
    }
    if (lane == 31) wsum[w] = xv;
    __syncthreads();
    if (w == 0) {
        int s = (lane < 8) ? wsum[lane] : 0;
        #pragma unroll
        for (int off = 1; off < 8; off <<= 1) {
            int t = __shfl_up_sync(0xffffffffu, s, off);
            if (lane >= off) s += t;
        }
        if (lane < 8) wsum[lane] = s;
    }
    __syncthreads();
    int incl = xv + ((w > 0) ? wsum[w - 1] : 0);
    if (i < n) g_rowstart[i] = incl;
    if (threadIdx.x == SB - 1) g_bsum[blockIdx.x] = incl;
}

// Level-2: one 512-thread block scans the NBLK1 block totals (exclusive).
__global__ void __launch_bounds__(512) k_scan2() {
    __shared__ int sh[512];
    int t = threadIdx.x;
    int v = (t < NBLK1) ? g_bsum[t] : 0;
    sh[t] = v;
    __syncthreads();
    for (int off = 1; off < 512; off <<= 1) {
        int tv = (t >= off) ? sh[t - off] : 0;
        __syncthreads();
        sh[t] += tv;
        __syncthreads();
    }
    if (t < NBLK1) g_boff[t] = sh[t] - v;   // exclusive prefix
}

__global__ void k_scan3(int n) {
    int i = blockIdx.x * blockDim.x + threadIdx.x;
    if (i < n) {
        int c = g_cnt[i];
        int start = g_rowstart[i] - c + g_boff[i / SB];
        g_rowstart[i] = start;
        g_cursor[i]   = start;
        g_dinv[i]     = rsqrtf((float)(c + 1));   // + self-loop
    }
}

__global__ void k_scatter(const int* __restrict__ src, const int* __restrict__ dst,
                          int E) {
    int e = blockIdx.x * blockDim.x + threadIdx.x;
    if (e < E) {
        unsigned d = (unsigned)dst[e];
        unsigned s = (unsigned)src[e];
        if (d < NN && s < NN) {
            int pos = atomicAdd(&g_cursor[d], 1);
            if ((unsigned)pos < EMAX) g_csr_src[pos] = (int)s;  // defensive
        }
    }
}

// Wc row k = W1[k,:] @ W2 ; block 128 computes bW = b1 @ W2.
__global__ void __launch_bounds__(64) k_small(const float* __restrict__ W1,
                                              const float* __restrict__ b1,
                                              const float* __restrict__ W2) {
    __shared__ float sA[INC];
    int k = blockIdx.x;
    const float* arow = (k < INC) ? (W1 + k * INC) : b1;
    for (int i = threadIdx.x; i < INC; i += 64) sA[i] = arow[i];
    __syncthreads();
    int c = threadIdx.x;
    float acc = 0.f;
    #pragma unroll 16
    for (int j = 0; j < INC; j++) acc += sA[j] * W2[j * FEAT + c];
    if (k < INC) g_Wc[k * FEAT + c] = acc;
    else         g_bW[c] = acc;
}

// H = X @ Wc, output fp16. One warp per row; lane computes cols 2l, 2l+1.
__global__ void __launch_bounds__(256) k_gemm(const float* __restrict__ x, int n) {
    __shared__ float sW[INC * FEAT];   // 32 KB
    __shared__ float sx[8][INC];
    for (int i = threadIdx.x; i < INC * FEAT; i += blockDim.x) sW[i] = g_Wc[i];
    __syncthreads();

    int w = threadIdx.x >> 5, lane = threadIdx.x & 31;
    const float2* sW2 = reinterpret_cast<const float2*>(sW);
    for (int row = blockIdx.x * 8 + w; row < n; row += gridDim.x * 8) {
        float4 xv = reinterpret_cast<const float4*>(x + (size_t)row * INC)[lane];
        sx[w][lane * 4 + 0] = xv.x;
        sx[w][lane * 4 + 1] = xv.y;
        sx[w][lane * 4 + 2] = xv.z;
        sx[w][lane * 4 + 3] = xv.w;
        __syncwarp();

        float a0 = 0.f, a1 = 0.f;
        #pragma unroll
        for (int k = 0; k < INC; k++) {
            float xk = sx[w][k];
            float2 wv = sW2[k * 32 + lane];   // cols 2*lane, 2*lane+1
            a0 += xk * wv.x;
            a1 += xk * wv.y;
        }
        reinterpret_cast<__half2*>(g_Hh + (size_t)row * FEAT)[lane] =
            __floats2half2_rn(a0, a1);
        __syncwarp();
    }
}

// ---------------------------------------------------------------------------
__device__ __forceinline__ void unpack8(uint4 u, float f[8]) {
    float2 a = __half22float2(*reinterpret_cast<__half2*>(&u.x));
    float2 b = __half22float2(*reinterpret_cast<__half2*>(&u.y));
    float2 c = __half22float2(*reinterpret_cast<__half2*>(&u.z));
    float2 d = __half22float2(*reinterpret_cast<__half2*>(&u.w));
    f[0] = a.x; f[1] = a.y; f[2] = b.x; f[3] = b.y;
    f[4] = c.x; f[5] = c.y; f[6] = d.x; f[7] = d.y;
}

__device__ __forceinline__ uint4 pack8(const float f[8]) {
    uint4 u;
    __half2 h0 = __floats2half2_rn(f[0], f[1]);
    __half2 h1 = __floats2half2_rn(f[2], f[3]);
    __half2 h2 = __floats2half2_rn(f[4], f[5]);
    __half2 h3 = __floats2half2_rn(f[6], f[7]);
    u.x = *reinterpret_cast<unsigned*>(&h0);
    u.y = *reinterpret_cast<unsigned*>(&h1);
    u.z = *reinterpret_cast<unsigned*>(&h2);
    u.w = *reinterpret_cast<unsigned*>(&h3);
    return u;
}

__device__ __forceinline__ void clamp_row(int& beg, int& cnt) {
    if (beg < 0 || beg >= EMAX) { beg = 0; cnt = 0; }
    if (cnt < 0) cnt = 0;
    if (cnt > EMAX - beg) cnt = EMAX - beg;
}

// CSR propagation 1 (fp16 gather, fp32 accum): T = A_hat @ H.
// 8 lanes per row, each lane owns 8 features (one uint4 = 16 B).
__global__ void __launch_bounds__(256) k_prop1(int n) {
    int t = blockIdx.x * 256 + threadIdx.x;
    int row = t >> 3;
    if (row >= n) return;
    int li = t & 7;
    const uint4* H = reinterpret_cast<const uint4*>(g_Hh);   // 8 uint4 per row
    float dv = g_dinv[row];
    int beg = g_rowstart[row], cnt = g_cnt[row];
    clamp_row(beg, cnt);

    float acc[8], f[8];
    unpack8(H[(size_t)row * 8 + li], acc);
    float d2 = dv * dv;
    #pragma unroll
    for (int j = 0; j < 8; j++) acc[j] *= d2;

    int k = 0;
    for (; k + 4 <= cnt; k += 4) {
        int s0 = g_csr_src[beg + k + 0];
        int s1 = g_csr_src[beg + k + 1];
        int s2 = g_csr_src[beg + k + 2];
        int s3 = g_csr_src[beg + k + 3];
        s0 = (unsigned)s0 < NN ? s0 : 0;  s1 = (unsigned)s1 < NN ? s1 : 0;
        s2 = (unsigned)s2 < NN ? s2 : 0;  s3 = (unsigned)s3 < NN ? s3 : 0;
        float n0 = dv * g_dinv[s0], n1 = dv * g_dinv[s1];
        float n2 = dv * g_dinv[s2], n3 = dv * g_dinv[s3];
        uint4 u0 = H[(size_t)s0 * 8 + li];
        uint4 u1 = H[(size_t)s1 * 8 + li];
        uint4 u2 = H[(size_t)s2 * 8 + li];
        uint4 u3 = H[(size_t)s3 * 8 + li];
        unpack8(u0, f);
        #pragma unroll
        for (int j = 0; j < 8; j++) acc[j] += f[j] * n0;
        unpack8(u1, f);
        #pragma unroll
        for (int j = 0; j < 8; j++) acc[j] += f[j] * n1;
        unpack8(u2, f);
        #pragma unroll
        for (int j = 0; j < 8; j++) acc[j] += f[j] * n2;
        unpack8(u3, f);
        #pragma unroll
        for (int j = 0; j < 8; j++) acc[j] += f[j] * n3;
    }
    for (; k < cnt; k++) {
        int s = g_csr_src[beg + k];
        s = (unsigned)s < NN ? s : 0;
        float nm = dv * g_dinv[s];
        unpack8(H[(size_t)s * 8 + li], f);
        #pragma unroll
        for (int j = 0; j < 8; j++) acc[j] += f[j] * nm;
    }
    reinterpret_cast<uint4*>(g_Th)[(size_t)row * 8 + li] = pack8(acc);
}

// CSR propagation 2 + epilogue (fp16 gather, fp32 accum + fp32 out):
// out[d] = dinv^2*T[d] + sum nm*T[s] + (dinv^2 + sum nm)*bW + b2
__global__ void __launch_bounds__(256) k_prop2(const float* __restrict__ b2,
                                               float* __restrict__ out, int n) {
    int t = blockIdx.x * 256 + threadIdx.x;
    int row = t >> 3;
    if (row >= n) return;
    int li = t & 7;
    const uint4* T = reinterpret_cast<const uint4*>(g_Th);
    float dv = g_dinv[row];
    int beg = g_rowstart[row], cnt = g_cnt[row];
    clamp_row(beg, cnt);

    float acc[8], f[8];
    unpack8(T[(size_t)row * 8 + li], acc);
    float d2 = dv * dv;
    float sn = d2;                        // row sum of A_hat
    #pragma unroll
    for (int j = 0; j < 8; j++) acc[j] *= d2;

    int k = 0;
    for (; k + 4 <= cnt; k += 4) {
        int s0 = g_csr_src[beg + k + 0];
        int s1 = g_csr_src[beg + k + 1];
        int s2 = g_csr_src[beg + k + 2];
        int s3 = g_csr_src[beg + k + 3];
        s0 = (unsigned)s0 < NN ? s0 : 0;  s1 = (unsigned)s1 < NN ? s1 : 0;
        s2 = (unsigned)s2 < NN ? s2 : 0;  s3 = (unsigned)s3 < NN ? s3 : 0;
        float n0 = dv * g_dinv[s0], n1 = dv * g_dinv[s1];
        float n2 = dv * g_dinv[s2], n3 = dv * g_dinv[s3];
        uint4 u0 = T[(size_t)s0 * 8 + li];
        uint4 u1 = T[(size_t)s1 * 8 + li];
        uint4 u2 = T[(size_t)s2 * 8 + li];
        uint4 u3 = T[(size_t)s3 * 8 + li];
        sn += n0 + n1 + n2 + n3;
        unpack8(u0, f);
        #pragma unroll
        for (int j = 0; j < 8; j++) acc[j] += f[j] * n0;
        unpack8(u1, f);
        #pragma unroll
        for (int j = 0; j < 8; j++) acc[j] += f[j] * n1;
        unpack8(u2, f);
        #pragma unroll
        for (int j = 0; j < 8; j++) acc[j] += f[j] * n2;
        unpack8(u3, f);
        #pragma unroll
        for (int j = 0; j < 8; j++) acc[j] += f[j] * n3;
    }
    for (; k < cnt; k++) {
        int s = g_csr_src[beg + k];
        s = (unsigned)s < NN ? s : 0;
        float nm = dv * g_dinv[s];
        unpack8(T[(size_t)s * 8 + li], f);
        sn += nm;
        #pragma unroll
        for (int j = 0; j < 8; j++) acc[j] += f[j] * nm;
    }

    float4 bwa = reinterpret_cast<const float4*>(g_bW)[li * 2 + 0];
    float4 bwb = reinterpret_cast<const float4*>(g_bW)[li * 2 + 1];
    float4 b2a = reinterpret_cast<const float4*>(b2)[li * 2 + 0];
    float4 b2b = reinterpret_cast<const float4*>(b2)[li * 2 + 1];
    float4 oa, ob;
    oa.x = acc[0] + sn * bwa.x + b2a.x;
    oa.y = acc[1] + sn * bwa.y + b2a.y;
    oa.z = acc[2] + sn * bwa.z + b2a.z;
    oa.w = acc[3] + sn * bwa.w + b2a.w;
    ob.x = acc[4] + sn * bwb.x + b2b.x;
    ob.y = acc[5] + sn * bwb.y + b2b.y;
    ob.z = acc[6] + sn * bwb.z + b2b.z;
    ob.w = acc[7] + sn * bwb.w + b2b.w;
    float4* op = reinterpret_cast<float4*>(out + (size_t)row * FEAT + li * 8);
    op[0] = oa;
    op[1] = ob;
}

// ---------------------------------------------------------------------------
extern "C" void kernel_launch(void* const* d_in, const int* in_sizes, int n_in,
                              void* d_out, int out_size) {
    const float* x   = (const float*)d_in[0];
    const int*   ei  = (const int*)d_in[1];    // int64 downcast to int32 by harness
    const float* W1  = (const float*)d_in[2];
    const float* b1  = (const float*)d_in[3];
    const float* W2  = (const float*)d_in[4];
    const float* b2  = (const float*)d_in[5];
    float* out = (float*)d_out;

    int n = in_sizes[0] / INC;          // 100000
    int E = in_sizes[1] / 2;            // 3200000
    const int* srcp = ei;
    const int* dstp = ei + E;

    k_zero<<<(n + 255) / 256, 256>>>(n);
    k_histo<<<(E + 255) / 256, 256>>>(dstp, E);
    k_scan1<<<NBLK1, SB>>>(n);
    k_scan2<<<1, 512>>>();
    k_scan3<<<(n + 255) / 256, 256>>>(n);
    k_scatter<<<(E + 255) / 256, 256>>>(srcp, dstp, E);
    k_small<<<INC + 1, 64>>>(W1, b1, W2);
    k_gemm<<<(n + 7) / 8, 256>>>(x, n);
    int pgrid = (n * 8 + 255) / 256;
    k_prop1<<<pgrid, 256>>>(n);
    k_prop2<<<pgrid, 256>>>(b2, out, n);
}